// round 12
// baseline (speedup 1.0000x reference)
#include <cuda_runtime.h>
#include <cuda_bf16.h>
#include <math.h>
#include <stdint.h>

// ---------------- problem constants ----------------
#define L_TOT 2048
#define B_TOT 32
#define H_TOT 128
#define P_TOT 256
#define T_CHK 64
#define C_CHK (L_TOT / T_CHK)       // 32 chunks
#define M_TOT (L_TOT * B_TOT)       // 65536 rows
#define NB2   512                   // Bu width in real floats (2*P)

// ---------------- scratch (device globals) ----------------
__device__ float    g_Bu[(size_t)M_TOT * NB2];     // 134 MB fp32 Bu
__device__ uint32_t g_ohw[(size_t)M_TOT * 256];    // o hi: bf16x2 words [m][256]
__device__ uint32_t g_olw[(size_t)M_TOT * 256];    // o lo
__device__ float2 g_Part[(size_t)C_CHK * 16 * B_TOT * P_TOT];  // per-m-tile weighted partials (32MB)
__device__ float2 g_Sloc[C_CHK * B_TOT * P_TOT];   // per-chunk aggregates
__device__ float2 g_Lam[P_TOT];
__device__ float2 g_LamT[P_TOT];
__device__ float2 g_LamPow[64 * P_TOT];            // lambda^e, e=0..63
__device__ float2 g_coeff[P_TOT];
// weights: separate hi/lo planes, n-major [n][k]
__device__ __nv_bfloat16 g_W1h[512 * 128];
__device__ __nv_bfloat16 g_W1l[512 * 128];
__device__ __nv_bfloat16 g_W2h[128 * 512];
__device__ __nv_bfloat16 g_W2l[128 * 512];

// ---------------- helpers ----------------
__device__ __forceinline__ void split_bf16(float v, __nv_bfloat16& h, __nv_bfloat16& l) {
    h = __float2bfloat16(v);
    l = __float2bfloat16(v - __bfloat162float(h));
}
__device__ __forceinline__ float2 cmul(float2 a, float2 b) {
    return make_float2(a.x * b.x - a.y * b.y, a.x * b.y + a.y * b.x);
}
__device__ __forceinline__ void mma16816(float* d, const uint32_t* a, const uint32_t* b) {
    asm volatile(
        "mma.sync.aligned.m16n8k16.row.col.f32.bf16.bf16.f32 "
        "{%0,%1,%2,%3}, {%4,%5,%6,%7}, {%8,%9}, {%0,%1,%2,%3};"
        : "+f"(d[0]), "+f"(d[1]), "+f"(d[2]), "+f"(d[3])
        : "r"(a[0]), "r"(a[1]), "r"(a[2]), "r"(a[3]), "r"(b[0]), "r"(b[1]));
}
__device__ __forceinline__ void ldsm4(uint32_t& r0, uint32_t& r1, uint32_t& r2, uint32_t& r3,
                                      uint32_t addr) {
    asm volatile("ldmatrix.sync.aligned.m8n8.x4.shared.b16 {%0,%1,%2,%3}, [%4];"
                 : "=r"(r0), "=r"(r1), "=r"(r2), "=r"(r3) : "r"(addr));
}
__device__ __forceinline__ uint32_t smem_u32(const void* p) {
    uint32_t a;
    asm("{ .reg .u64 t; cvta.to.shared.u64 t, %1; cvt.u32.u64 %0, t; }" : "=r"(a) : "l"(p));
    return a;
}
#define CP_ASYNC16(dst, src) \
    asm volatile("cp.async.cg.shared.global [%0], [%1], 16;" :: "r"(dst), "l"(src))
#define CP_COMMIT() asm volatile("cp.async.commit_group;" ::: "memory")
#define CP_WAIT0()  asm volatile("cp.async.wait_group 0;" ::: "memory")

// SMEM tile geometry: rows of 40 bf16 (80 B stride), 128 rows/tile
#define TILE_B (128 * 40 * 2)      // 10240 B
#define OF_AH 0
#define OF_AL TILE_B
#define OF_BH (2 * TILE_B)
#define OF_BL (3 * TILE_B)
#define BUF_B (4 * TILE_B)         // 40960 B per stage
#define SMEM_TOTAL (2 * BUF_B)     // 81920 B

// ---------------- K0a: per-p scalar precompute ----------------
__global__ void precompute_a(const float* __restrict__ lLr, const float* __restrict__ Li,
                             const float* __restrict__ lDelta) {
    int p = threadIdx.x;
    double lamr = -exp((double)lLr[p]);
    double lami = (double)Li[p];
    double dt = exp((double)lDelta[p]);
    double lbr = lamr * dt, lbi = lami * dt;
    double er = exp(lbr);
    double Lr = er * cos(lbi), Limg = er * sin(lbi);
    g_Lam[p] = make_float2((float)Lr, (float)Limg);
    double eT = exp((double)T_CHK * lbr);
    g_LamT[p] = make_float2((float)(eT * cos((double)T_CHK * lbi)),
                            (float)(eT * sin((double)T_CHK * lbi)));
    for (int e = 0; e < 64; e++) {
        double ee = exp(e * lbr);
        g_LamPow[e * P_TOT + p] =
            make_float2((float)(ee * cos(e * lbi)), (float)(ee * sin(e * lbi)));
    }
    double nr = Lr - 1.0, ni = Limg;
    double den = lamr * lamr + lami * lami;
    g_coeff[p] = make_float2((float)((nr * lamr + ni * lami) / den),
                             (float)((ni * lamr - nr * lami) / den));
}

// ---------------- K0b: pack weights into hi/lo planes ----------------
__global__ __launch_bounds__(256) void precompute_w(
    const float* __restrict__ Br, const float* __restrict__ Bi,
    const float* __restrict__ Cr, const float* __restrict__ Ci) {
    int idx = blockIdx.x * 256 + threadIdx.x;  // 32768 = 128 h x 256 p
    int h = idx >> 8, p = idx & 255;
    float2 cf = g_coeff[p];
    float br = Br[p * H_TOT + h], bi = Bi[p * H_TOT + h];
    float w1v[2] = {cf.x * br - cf.y * bi, cf.x * bi + cf.y * br};
#pragma unroll
    for (int j = 0; j < 2; j++) {
        int n = 2 * p + j;
        __nv_bfloat16 hh, ll;
        split_bf16(w1v[j], hh, ll);
        g_W1h[(size_t)n * 128 + h] = hh;
        g_W1l[(size_t)n * 128 + h] = ll;
    }
    float w2v[2] = {Cr[h * P_TOT + p], -Ci[h * P_TOT + p]};
#pragma unroll
    for (int j = 0; j < 2; j++) {
        int k = 2 * p + j;
        __nv_bfloat16 hh, ll;
        split_bf16(w2v[j], hh, ll);
        g_W2h[(size_t)h * 512 + k] = hh;
        g_W2l[(size_t)h * 512 + k] = ll;
    }
}

// ---------------- shared MMA inner step (ldmatrix version) ----------------
__device__ __forceinline__ void mma_chunk(uint32_t sbuf, int wm, int wn, int lane,
                                          float acc[2][8][4]) {
    int g = lane >> 3, rg = lane & 7;
#pragma unroll
    for (int kk = 0; kk < 2; kk++) {
        int k16 = kk * 16;
        uint32_t ah[2][4], al[2][4];
#pragma unroll
        for (int mt = 0; mt < 2; mt++) {
            int row = wm * 32 + mt * 16 + (g & 1) * 8 + rg;
            int col = k16 + (g >> 1) * 8;
            uint32_t a = sbuf + row * 80 + col * 2;
            ldsm4(ah[mt][0], ah[mt][1], ah[mt][2], ah[mt][3], a + OF_AH);
            ldsm4(al[mt][0], al[mt][1], al[mt][2], al[mt][3], a + OF_AL);
        }
        uint32_t b[8][2];
        {
            int row = wn * 64 + (g >> 1) * 8 + rg;
            int col = k16 + (g & 1) * 8;
#pragma unroll
            for (int np = 0; np < 4; np++) {
                uint32_t ba = sbuf + OF_BH + (row + np * 16) * 80 + col * 2;
                ldsm4(b[2 * np][0], b[2 * np][1], b[2 * np + 1][0], b[2 * np + 1][1], ba);
            }
#pragma unroll
            for (int mt = 0; mt < 2; mt++)
#pragma unroll
                for (int nt = 0; nt < 8; nt++) {
                    mma16816(acc[mt][nt], ah[mt], b[nt]);
                    mma16816(acc[mt][nt], al[mt], b[nt]);
                }
#pragma unroll
            for (int np = 0; np < 4; np++) {
                uint32_t ba = sbuf + OF_BL + (row + np * 16) * 80 + col * 2;
                ldsm4(b[2 * np][0], b[2 * np][1], b[2 * np + 1][0], b[2 * np + 1][1], ba);
            }
#pragma unroll
            for (int mt = 0; mt < 2; mt++)
#pragma unroll
                for (int nt = 0; nt < 8; nt++)
                    mma16816(acc[mt][nt], ah[mt], b[nt]);
        }
    }
}

// ---------------- GEMM1: Bu = u @ W1 + fused chunk-aggregate partials ----------------
__global__ __launch_bounds__(256, 2) void gemm1_mma(const float* __restrict__ u) {
    extern __shared__ char smem[];
    uint32_t sb = smem_u32(smem);
    int tid = threadIdx.x, lane = tid & 31, wid = tid >> 5;
    int gq = lane >> 2, tig = lane & 3;
    int wm = wid >> 1, wn = wid & 1;
    int bn = blockIdx.x * 128, bm = blockIdx.y * 128;

    float acc[2][8][4];
#pragma unroll
    for (int mt = 0; mt < 2; mt++)
#pragma unroll
        for (int nt = 0; nt < 8; nt++)
#pragma unroll
            for (int i = 0; i < 4; i++) acc[mt][nt][i] = 0.f;

    float4 areg[4];
#pragma unroll
    for (int i = 0; i < 4; i++) {
        int idx = tid + i * 256;
        int row = idx >> 3, c4 = (idx & 7) * 4;
        areg[i] = *(const float4*)(u + (size_t)(bm + row) * 128 + 0 + c4);
    }
#pragma unroll
    for (int i = 0; i < 2; i++) {
        int idx = tid + i * 256;
        int row = idx >> 2, seg = idx & 3;
        CP_ASYNC16(sb + OF_BH + row * 80 + seg * 16,
                   g_W1h + (size_t)(bn + row) * 128 + seg * 8);
        CP_ASYNC16(sb + OF_BL + row * 80 + seg * 16,
                   g_W1l + (size_t)(bn + row) * 128 + seg * 8);
    }
    CP_COMMIT();

    for (int kt = 0; kt < 4; kt++) {
        int b = kt & 1;
        char* buf = smem + b * BUF_B;
#pragma unroll
        for (int i = 0; i < 4; i++) {
            int idx = tid + i * 256;
            int row = idx >> 3, c4 = (idx & 7) * 4;
            float4 v = areg[i];
            __nv_bfloat162 h01, h23, l01, l23;
            split_bf16(v.x, h01.x, l01.x);
            split_bf16(v.y, h01.y, l01.y);
            split_bf16(v.z, h23.x, l23.x);
            split_bf16(v.w, h23.y, l23.y);
            *(uint2*)(buf + OF_AH + row * 80 + c4 * 2) =
                make_uint2(*(uint32_t*)&h01, *(uint32_t*)&h23);
            *(uint2*)(buf + OF_AL + row * 80 + c4 * 2) =
                make_uint2(*(uint32_t*)&l01, *(uint32_t*)&l23);
        }
        if (kt < 3) {
#pragma unroll
            for (int i = 0; i < 4; i++) {
                int idx = tid + i * 256;
                int row = idx >> 3, c4 = (idx & 7) * 4;
                areg[i] = *(const float4*)(u + (size_t)(bm + row) * 128 + (kt + 1) * 32 + c4);
            }
        }
        CP_WAIT0();
        __syncthreads();
        if (kt < 3) {
            uint32_t nb = sb + (b ^ 1) * BUF_B;
#pragma unroll
            for (int i = 0; i < 2; i++) {
                int idx = tid + i * 256;
                int row = idx >> 2, seg = idx & 3;
                CP_ASYNC16(nb + OF_BH + row * 80 + seg * 16,
                           g_W1h + (size_t)(bn + row) * 128 + (kt + 1) * 32 + seg * 8);
                CP_ASYNC16(nb + OF_BL + row * 80 + seg * 16,
                           g_W1l + (size_t)(bn + row) * 128 + (kt + 1) * 32 + seg * 8);
            }
            CP_COMMIT();
        }
        mma_chunk(sb + b * BUF_B, wm, wn, lane, acc);
    }
    // Bu store
#pragma unroll
    for (int mt = 0; mt < 2; mt++)
#pragma unroll
        for (int nt = 0; nt < 8; nt++) {
            int r = bm + wm * 32 + mt * 16 + gq;
            int c = bn + wn * 64 + nt * 8 + 2 * tig;
            *(float2*)&g_Bu[(size_t)r * NB2 + c] = make_float2(acc[mt][nt][0], acc[mt][nt][1]);
            *(float2*)&g_Bu[(size_t)(r + 8) * NB2 + c] = make_float2(acc[mt][nt][2], acc[mt][nt][3]);
        }
    // fused aggregate partial: each warp's rows are one timestep t = blockIdx.y*4 + wm
    __syncthreads();
    float2* red = (float2*)smem;   // [wm][wn][b(32)][pl(32)] = 64KB
    {
        int tl = (blockIdx.y & 15) * 4 + wm;
        int e = 63 - tl;
        float2 w[8];
#pragma unroll
        for (int nt = 0; nt < 8; nt++)
            w[nt] = g_LamPow[e * P_TOT + (bn >> 1) + wn * 32 + nt * 4 + tig];
#pragma unroll
        for (int mt = 0; mt < 2; mt++)
#pragma unroll
            for (int nt = 0; nt < 8; nt++)
#pragma unroll
                for (int half = 0; half < 2; half++) {
                    int b = mt * 16 + gq + half * 8;
                    int pl = nt * 4 + tig;
                    float2 v = make_float2(acc[mt][nt][2 * half], acc[mt][nt][2 * half + 1]);
                    red[((wm * 2 + wn) * 32 + b) * 32 + pl] = cmul(w[nt], v);
                }
    }
    __syncthreads();
    {
        int cch = blockIdx.y >> 4, sub = blockIdx.y & 15;
#pragma unroll
        for (int i = 0; i < 8; i++) {
            int slot = tid * 8 + i;               // (wn, b, pl)
            int wnn = slot >> 10, b = (slot >> 5) & 31, pl = slot & 31;
            float2 s = make_float2(0.f, 0.f);
#pragma unroll
            for (int wmm = 0; wmm < 4; wmm++) {
                float2 a = red[((wmm * 2 + wnn) * 32 + b) * 32 + pl];
                s.x += a.x; s.y += a.y;
            }
            int pg = (bn >> 1) + wnn * 32 + pl;
            g_Part[((size_t)(cch * 16 + sub) * 32 + b) * 256 + pg] = s;
        }
    }
}

// ---------------- K2: reduce partials -> chunk aggregates ----------------
__global__ __launch_bounds__(256) void reduce_part() {
    int idx = blockIdx.x * 256 + threadIdx.x;   // 262144 = (c,b,p)
    int p = idx & 255, b = (idx >> 8) & 31, c = idx >> 13;
    float2 s = make_float2(0.f, 0.f);
#pragma unroll
    for (int sub = 0; sub < 16; sub++) {
        float2 a = g_Part[((size_t)(c * 16 + sub) * 32 + b) * 256 + p];
        s.x += a.x; s.y += a.y;
    }
    g_Sloc[((size_t)c * B_TOT + b) * P_TOT + p] = s;
}

// ---------------- K3: final scan (2 p per thread), inline prefix, emit bf16 hi/lo ----------------
__global__ __launch_bounds__(256) void scan_final_kernel() {
    int tid = threadIdx.x;
    int p2 = (tid & 127) * 2;
    int b = ((blockIdx.x & 15) << 1) + (tid >> 7);
    int c = blockIdx.x >> 4;

    float4 lp = *(const float4*)&g_Lam[p2];
    float2 lam0 = make_float2(lp.x, lp.y), lam1 = make_float2(lp.z, lp.w);
    float2 s0 = make_float2(0.f, 0.f), s1 = make_float2(0.f, 0.f);
    // inline prefix over prior chunk aggregates
    {
        float4 l64 = *(const float4*)&g_LamT[p2];
        float2 l640 = make_float2(l64.x, l64.y), l641 = make_float2(l64.z, l64.w);
        float2 f0 = make_float2(1.f, 0.f), f1 = make_float2(1.f, 0.f);
        for (int j = c - 1; j >= 0; j--) {
            float4 a = *(const float4*)&g_Sloc[((size_t)j * B_TOT + b) * P_TOT + p2];
            float2 t0 = cmul(f0, make_float2(a.x, a.y));
            float2 t1 = cmul(f1, make_float2(a.z, a.w));
            s0.x += t0.x; s0.y += t0.y;
            s1.x += t1.x; s1.y += t1.y;
            f0 = cmul(f0, l640);
            f1 = cmul(f1, l641);
        }
    }
    const float2* bu = (const float2*)g_Bu;
    size_t mbase = (size_t)(c * T_CHK) * B_TOT + b;
#pragma unroll 4
    for (int t = 0; t < T_CHK; t++) {
        size_t m = mbase + (size_t)t * B_TOT;
        float4 x = *(const float4*)&bu[m * 256 + p2];
        s0 = cmul(lam0, s0);
        s0.x += x.x; s0.y += x.y;
        s1 = cmul(lam1, s1);
        s1.x += x.z; s1.y += x.w;
        __nv_bfloat162 h0, l0, h1, l1;
        split_bf16(s0.x, h0.x, l0.x);
        split_bf16(s0.y, h0.y, l0.y);
        split_bf16(s1.x, h1.x, l1.x);
        split_bf16(s1.y, h1.y, l1.y);
        *(uint2*)&g_ohw[m * 256 + p2] = make_uint2(*(uint32_t*)&h0, *(uint32_t*)&h1);
        *(uint2*)&g_olw[m * 256 + p2] = make_uint2(*(uint32_t*)&l0, *(uint32_t*)&l1);
    }
}

// ---------------- GEMM2: out = o @ W2 + D*u (M=65536, N=128, K=512; 16 kt) ----------------
__global__ __launch_bounds__(256, 2) void gemm2_mma(const float* __restrict__ u,
                                                    const float* __restrict__ Dv,
                                                    float* __restrict__ out) {
    extern __shared__ char smem[];
    uint32_t sb = smem_u32(smem);
    int tid = threadIdx.x, lane = tid & 31, wid = tid >> 5;
    int gq = lane >> 2, tig = lane & 3;
    int wm = wid >> 1, wn = wid & 1;
    int bm = blockIdx.x * 128;

    float acc[2][8][4];
#pragma unroll
    for (int mt = 0; mt < 2; mt++)
#pragma unroll
        for (int nt = 0; nt < 8; nt++)
#pragma unroll
            for (int i = 0; i < 4; i++) acc[mt][nt][i] = 0.f;

#pragma unroll
    for (int i = 0; i < 2; i++) {
        int idx = tid + i * 256;
        int row = idx >> 2, seg = idx & 3;
        CP_ASYNC16(sb + OF_AH + row * 80 + seg * 16, g_ohw + (size_t)(bm + row) * 256 + seg * 4);
        CP_ASYNC16(sb + OF_AL + row * 80 + seg * 16, g_olw + (size_t)(bm + row) * 256 + seg * 4);
        CP_ASYNC16(sb + OF_BH + row * 80 + seg * 16, g_W2h + (size_t)row * 512 + seg * 8);
        CP_ASYNC16(sb + OF_BL + row * 80 + seg * 16, g_W2l + (size_t)row * 512 + seg * 8);
    }
    CP_COMMIT();

    for (int kt = 0; kt < 16; kt++) {
        int b = kt & 1;
        CP_WAIT0();
        __syncthreads();
        if (kt < 15) {
            uint32_t nb = sb + (b ^ 1) * BUF_B;
            int kn = kt + 1;
#pragma unroll
            for (int i = 0; i < 2; i++) {
                int idx = tid + i * 256;
                int row = idx >> 2, seg = idx & 3;
                CP_ASYNC16(nb + OF_AH + row * 80 + seg * 16,
                           g_ohw + (size_t)(bm + row) * 256 + kn * 16 + seg * 4);
                CP_ASYNC16(nb + OF_AL + row * 80 + seg * 16,
                           g_olw + (size_t)(bm + row) * 256 + kn * 16 + seg * 4);
                CP_ASYNC16(nb + OF_BH + row * 80 + seg * 16,
                           g_W2h + (size_t)row * 512 + kn * 32 + seg * 8);
                CP_ASYNC16(nb + OF_BL + row * 80 + seg * 16,
                           g_W2l + (size_t)row * 512 + kn * 32 + seg * 8);
            }
            CP_COMMIT();
        }
        mma_chunk(sb + b * BUF_B, wm, wn, lane, acc);
    }
#pragma unroll
    for (int mt = 0; mt < 2; mt++)
#pragma unroll
        for (int nt = 0; nt < 8; nt++) {
            int c = wn * 64 + nt * 8 + 2 * tig;
            float2 dv = *(const float2*)(Dv + c);
#pragma unroll
            for (int half = 0; half < 2; half++) {
                int r = bm + wm * 32 + mt * 16 + gq + half * 8;
                float2 uv = *(const float2*)(u + (size_t)r * 128 + c);
                float2 o;
                o.x = acc[mt][nt][2 * half + 0] + dv.x * uv.x;
                o.y = acc[mt][nt][2 * half + 1] + dv.y * uv.y;
                *(float2*)&out[(size_t)r * 128 + c] = o;
            }
        }
}

// ---------------- launch ----------------
extern "C" void kernel_launch(void* const* d_in, const int* in_sizes, int n_in,
                              void* d_out, int out_size) {
    const float* u   = (const float*)d_in[0];
    const float* lLr = (const float*)d_in[1];
    const float* Li  = (const float*)d_in[2];
    const float* Br  = (const float*)d_in[3];
    const float* Bi  = (const float*)d_in[4];
    const float* Cr  = (const float*)d_in[5];
    const float* Ci  = (const float*)d_in[6];
    const float* Dv  = (const float*)d_in[7];
    const float* lDt = (const float*)d_in[8];
    float* out = (float*)d_out;

    cudaFuncSetAttribute(gemm1_mma, cudaFuncAttributeMaxDynamicSharedMemorySize, SMEM_TOTAL);
    cudaFuncSetAttribute(gemm2_mma, cudaFuncAttributeMaxDynamicSharedMemorySize, SMEM_TOTAL);

    precompute_a<<<1, 256>>>(lLr, Li, lDt);
    precompute_w<<<128, 256>>>(Br, Bi, Cr, Ci);

    gemm1_mma<<<dim3(4, M_TOT / 128), 256, SMEM_TOTAL>>>(u);

    reduce_part<<<1024, 256>>>();
    scan_final_kernel<<<C_CHK * 16, 256>>>();

    gemm2_mma<<<M_TOT / 128, 256, SMEM_TOTAL>>>(u, Dv, out);
}

// round 13
// speedup vs baseline: 3.2488x; 3.2488x over previous
#include <cuda_runtime.h>
#include <cuda_bf16.h>
#include <math.h>
#include <stdint.h>

// ---------------- problem constants ----------------
#define L_TOT 2048
#define B_TOT 32
#define H_TOT 128
#define P_TOT 256
#define T_CHK 64
#define C_CHK (L_TOT / T_CHK)       // 32 chunks
#define M_TOT (L_TOT * B_TOT)       // 65536 rows
#define NB2   512                   // Bu width in real floats (2*P)

// ---------------- scratch (device globals) ----------------
__device__ float    g_Bu[(size_t)M_TOT * NB2];     // 134 MB fp32 Bu -> consumed by scan
__device__ uint32_t g_ohw[(size_t)M_TOT * 256];    // o hi: bf16x2 words [m][256]
__device__ uint32_t g_olw[(size_t)M_TOT * 256];    // o lo
__device__ float2 g_Sloc[C_CHK * B_TOT * P_TOT];   // per-chunk local aggregates
__device__ float2 g_Lam[P_TOT];
__device__ float2 g_LamT[P_TOT];
__device__ float2 g_coeff[P_TOT];
// weights: separate hi/lo planes, n-major [n][k]
__device__ __nv_bfloat16 g_W1h[512 * 128];
__device__ __nv_bfloat16 g_W1l[512 * 128];
__device__ __nv_bfloat16 g_W2h[128 * 512];
__device__ __nv_bfloat16 g_W2l[128 * 512];

// ---------------- helpers ----------------
__device__ __forceinline__ void split_bf16(float v, __nv_bfloat16& h, __nv_bfloat16& l) {
    h = __float2bfloat16(v);
    l = __float2bfloat16(v - __bfloat162float(h));
}
__device__ __forceinline__ float2 cmul(float2 a, float2 b) {
    return make_float2(a.x * b.x - a.y * b.y, a.x * b.y + a.y * b.x);
}
__device__ __forceinline__ void mma16816(float* d, const uint32_t* a, const uint32_t* b) {
    asm volatile(
        "mma.sync.aligned.m16n8k16.row.col.f32.bf16.bf16.f32 "
        "{%0,%1,%2,%3}, {%4,%5,%6,%7}, {%8,%9}, {%0,%1,%2,%3};"
        : "+f"(d[0]), "+f"(d[1]), "+f"(d[2]), "+f"(d[3])
        : "r"(a[0]), "r"(a[1]), "r"(a[2]), "r"(a[3]), "r"(b[0]), "r"(b[1]));
}
__device__ __forceinline__ void ldsm4(uint32_t& r0, uint32_t& r1, uint32_t& r2, uint32_t& r3,
                                      uint32_t addr) {
    asm volatile("ldmatrix.sync.aligned.m8n8.x4.shared.b16 {%0,%1,%2,%3}, [%4];"
                 : "=r"(r0), "=r"(r1), "=r"(r2), "=r"(r3) : "r"(addr));
}
__device__ __forceinline__ uint32_t smem_u32(const void* p) {
    uint32_t a;
    asm("{ .reg .u64 t; cvta.to.shared.u64 t, %1; cvt.u32.u64 %0, t; }" : "=r"(a) : "l"(p));
    return a;
}
#define CP_ASYNC16(dst, src) \
    asm volatile("cp.async.cg.shared.global [%0], [%1], 16;" :: "r"(dst), "l"(src))
#define CP_COMMIT() asm volatile("cp.async.commit_group;" ::: "memory")
#define CP_WAIT0()  asm volatile("cp.async.wait_group 0;" ::: "memory")

// SMEM tile geometry: rows of 40 bf16 (80 B stride), 128 rows/tile
#define TILE_B (128 * 40 * 2)      // 10240 B
#define OF_AH 0
#define OF_AL TILE_B
#define OF_BH (2 * TILE_B)
#define OF_BL (3 * TILE_B)
#define BUF_B (4 * TILE_B)         // 40960 B per stage
#define SMEM_TOTAL (2 * BUF_B)     // 81920 B

// ---------------- K0a: per-p scalar precompute ----------------
__global__ void precompute_a(const float* __restrict__ lLr, const float* __restrict__ Li,
                             const float* __restrict__ lDelta) {
    int p = threadIdx.x;
    double lamr = -exp((double)lLr[p]);
    double lami = (double)Li[p];
    double dt = exp((double)lDelta[p]);
    double lbr = lamr * dt, lbi = lami * dt;
    double er = exp(lbr);
    double Lr = er * cos(lbi), Limg = er * sin(lbi);
    g_Lam[p] = make_float2((float)Lr, (float)Limg);
    double eT = exp((double)T_CHK * lbr);
    g_LamT[p] = make_float2((float)(eT * cos((double)T_CHK * lbi)),
                            (float)(eT * sin((double)T_CHK * lbi)));
    double nr = Lr - 1.0, ni = Limg;
    double den = lamr * lamr + lami * lami;
    g_coeff[p] = make_float2((float)((nr * lamr + ni * lami) / den),
                             (float)((ni * lamr - nr * lami) / den));
}

// ---------------- K0b: pack weights into hi/lo planes ----------------
__global__ __launch_bounds__(256) void precompute_w(
    const float* __restrict__ Br, const float* __restrict__ Bi,
    const float* __restrict__ Cr, const float* __restrict__ Ci) {
    int idx = blockIdx.x * 256 + threadIdx.x;  // 32768 = 128 h x 256 p
    int h = idx >> 8, p = idx & 255;
    float2 cf = g_coeff[p];
    float br = Br[p * H_TOT + h], bi = Bi[p * H_TOT + h];
    float w1v[2] = {cf.x * br - cf.y * bi, cf.x * bi + cf.y * br};
#pragma unroll
    for (int j = 0; j < 2; j++) {
        int n = 2 * p + j;
        __nv_bfloat16 hh, ll;
        split_bf16(w1v[j], hh, ll);
        g_W1h[(size_t)n * 128 + h] = hh;
        g_W1l[(size_t)n * 128 + h] = ll;
    }
    float w2v[2] = {Cr[h * P_TOT + p], -Ci[h * P_TOT + p]};
#pragma unroll
    for (int j = 0; j < 2; j++) {
        int k = 2 * p + j;
        __nv_bfloat16 hh, ll;
        split_bf16(w2v[j], hh, ll);
        g_W2h[(size_t)h * 512 + k] = hh;
        g_W2l[(size_t)h * 512 + k] = ll;
    }
}

// ---------------- shared MMA inner step (ldmatrix version) ----------------
// acc += Ah*Bh + Al*Bh + Ah*Bl over one 32-wide K chunk at smem u32 base `sbuf`
__device__ __forceinline__ void mma_chunk(uint32_t sbuf, int wm, int wn, int lane,
                                          float acc[2][8][4]) {
    int g = lane >> 3, rg = lane & 7;
#pragma unroll
    for (int kk = 0; kk < 2; kk++) {
        int k16 = kk * 16;
        uint32_t ah[2][4], al[2][4];
#pragma unroll
        for (int mt = 0; mt < 2; mt++) {
            int row = wm * 32 + mt * 16 + (g & 1) * 8 + rg;
            int col = k16 + (g >> 1) * 8;
            uint32_t a = sbuf + row * 80 + col * 2;
            ldsm4(ah[mt][0], ah[mt][1], ah[mt][2], ah[mt][3], a + OF_AH);
            ldsm4(al[mt][0], al[mt][1], al[mt][2], al[mt][3], a + OF_AL);
        }
        uint32_t b[8][2];
        {
            int row = wn * 64 + (g >> 1) * 8 + rg;
            int col = k16 + (g & 1) * 8;
#pragma unroll
            for (int np = 0; np < 4; np++) {
                uint32_t ba = sbuf + OF_BH + (row + np * 16) * 80 + col * 2;
                ldsm4(b[2 * np][0], b[2 * np][1], b[2 * np + 1][0], b[2 * np + 1][1], ba);
            }
#pragma unroll
            for (int mt = 0; mt < 2; mt++)
#pragma unroll
                for (int nt = 0; nt < 8; nt++) {
                    mma16816(acc[mt][nt], ah[mt], b[nt]);
                    mma16816(acc[mt][nt], al[mt], b[nt]);
                }
#pragma unroll
            for (int np = 0; np < 4; np++) {
                uint32_t ba = sbuf + OF_BL + (row + np * 16) * 80 + col * 2;
                ldsm4(b[2 * np][0], b[2 * np][1], b[2 * np + 1][0], b[2 * np + 1][1], ba);
            }
#pragma unroll
            for (int mt = 0; mt < 2; mt++)
#pragma unroll
                for (int nt = 0; nt < 8; nt++)
                    mma16816(acc[mt][nt], ah[mt], b[nt]);
        }
    }
}

// ---------------- GEMM1: Bu = u @ W1 (M=65536, N=512, K=128; 4 kt) ----------------
__global__ __launch_bounds__(256, 2) void gemm1_mma(const float* __restrict__ u) {
    extern __shared__ char smem[];
    uint32_t sb = smem_u32(smem);
    int tid = threadIdx.x, lane = tid & 31, wid = tid >> 5;
    int gq = lane >> 2, tig = lane & 3;
    int wm = wid >> 1, wn = wid & 1;
    int bn = blockIdx.x * 128, bm = blockIdx.y * 128;

    float acc[2][8][4];
#pragma unroll
    for (int mt = 0; mt < 2; mt++)
#pragma unroll
        for (int nt = 0; nt < 8; nt++)
#pragma unroll
            for (int i = 0; i < 4; i++) acc[mt][nt][i] = 0.f;

    float4 areg[4];
#pragma unroll
    for (int i = 0; i < 4; i++) {
        int idx = tid + i * 256;
        int row = idx >> 3, c4 = (idx & 7) * 4;
        areg[i] = *(const float4*)(u + (size_t)(bm + row) * 128 + 0 + c4);
    }
#pragma unroll
    for (int i = 0; i < 2; i++) {
        int idx = tid + i * 256;
        int row = idx >> 2, seg = idx & 3;
        CP_ASYNC16(sb + OF_BH + row * 80 + seg * 16,
                   g_W1h + (size_t)(bn + row) * 128 + seg * 8);
        CP_ASYNC16(sb + OF_BL + row * 80 + seg * 16,
                   g_W1l + (size_t)(bn + row) * 128 + seg * 8);
    }
    CP_COMMIT();

    for (int kt = 0; kt < 4; kt++) {
        int b = kt & 1;
        char* buf = smem + b * BUF_B;
#pragma unroll
        for (int i = 0; i < 4; i++) {
            int idx = tid + i * 256;
            int row = idx >> 3, c4 = (idx & 7) * 4;
            float4 v = areg[i];
            __nv_bfloat162 h01, h23, l01, l23;
            split_bf16(v.x, h01.x, l01.x);
            split_bf16(v.y, h01.y, l01.y);
            split_bf16(v.z, h23.x, l23.x);
            split_bf16(v.w, h23.y, l23.y);
            *(uint2*)(buf + OF_AH + row * 80 + c4 * 2) =
                make_uint2(*(uint32_t*)&h01, *(uint32_t*)&h23);
            *(uint2*)(buf + OF_AL + row * 80 + c4 * 2) =
                make_uint2(*(uint32_t*)&l01, *(uint32_t*)&l23);
        }
        if (kt < 3) {
#pragma unroll
            for (int i = 0; i < 4; i++) {
                int idx = tid + i * 256;
                int row = idx >> 3, c4 = (idx & 7) * 4;
                areg[i] = *(const float4*)(u + (size_t)(bm + row) * 128 + (kt + 1) * 32 + c4);
            }
        }
        CP_WAIT0();
        __syncthreads();
        if (kt < 3) {
            uint32_t nb = sb + (b ^ 1) * BUF_B;
#pragma unroll
            for (int i = 0; i < 2; i++) {
                int idx = tid + i * 256;
                int row = idx >> 2, seg = idx & 3;
                CP_ASYNC16(nb + OF_BH + row * 80 + seg * 16,
                           g_W1h + (size_t)(bn + row) * 128 + (kt + 1) * 32 + seg * 8);
                CP_ASYNC16(nb + OF_BL + row * 80 + seg * 16,
                           g_W1l + (size_t)(bn + row) * 128 + (kt + 1) * 32 + seg * 8);
            }
            CP_COMMIT();
        }
        mma_chunk(sb + b * BUF_B, wm, wn, lane, acc);
    }
#pragma unroll
    for (int mt = 0; mt < 2; mt++)
#pragma unroll
        for (int nt = 0; nt < 8; nt++) {
            int r = bm + wm * 32 + mt * 16 + gq;
            int c = bn + wn * 64 + nt * 8 + 2 * tig;
            *(float2*)&g_Bu[(size_t)r * NB2 + c] = make_float2(acc[mt][nt][0], acc[mt][nt][1]);
            *(float2*)&g_Bu[(size_t)(r + 8) * NB2 + c] = make_float2(acc[mt][nt][2], acc[mt][nt][3]);
        }
}

// ---------------- K2: per-chunk local scan (vectorized: 2 p per thread) ----------------
// grid: C_CHK*16 blocks (c, b-pair), 256 threads: b = pair*2 + (tid>>7), p2 = (tid&127)*2
__global__ __launch_bounds__(256) void scan_local_kernel() {
    int tid = threadIdx.x;
    int p2 = (tid & 127) * 2;
    int b = ((blockIdx.x & 15) << 1) + (tid >> 7);
    int c = blockIdx.x >> 4;

    float4 lp = *(const float4*)&g_Lam[p2];
    float2 lam0 = make_float2(lp.x, lp.y), lam1 = make_float2(lp.z, lp.w);
    float2 s0 = make_float2(0.f, 0.f), s1 = make_float2(0.f, 0.f);
    const float2* bu = (const float2*)g_Bu;
    size_t mbase = (size_t)(c * T_CHK) * B_TOT + b;
#pragma unroll 8
    for (int t = 0; t < T_CHK; t++) {
        float4 x = *(const float4*)&bu[(mbase + (size_t)t * B_TOT) * 256 + p2];
        s0 = cmul(lam0, s0);
        s0.x += x.x; s0.y += x.y;
        s1 = cmul(lam1, s1);
        s1.x += x.z; s1.y += x.w;
    }
    float4 outv = make_float4(s0.x, s0.y, s1.x, s1.y);
    *(float4*)&g_Sloc[((size_t)c * B_TOT + b) * P_TOT + p2] = outv;
}

// ---------------- K3: final scan (2 p per thread), inline prefix, emit bf16 hi/lo ----------------
__global__ __launch_bounds__(256) void scan_final_kernel() {
    int tid = threadIdx.x;
    int p2 = (tid & 127) * 2;
    int b = ((blockIdx.x & 15) << 1) + (tid >> 7);
    int c = blockIdx.x >> 4;

    float4 lp = *(const float4*)&g_Lam[p2];
    float2 lam0 = make_float2(lp.x, lp.y), lam1 = make_float2(lp.z, lp.w);
    float2 s0 = make_float2(0.f, 0.f), s1 = make_float2(0.f, 0.f);
    // inline prefix over prior chunk aggregates
    {
        float4 l64 = *(const float4*)&g_LamT[p2];
        float2 l640 = make_float2(l64.x, l64.y), l641 = make_float2(l64.z, l64.w);
        float2 f0 = make_float2(1.f, 0.f), f1 = make_float2(1.f, 0.f);
        for (int j = c - 1; j >= 0; j--) {
            float4 a = *(const float4*)&g_Sloc[((size_t)j * B_TOT + b) * P_TOT + p2];
            float2 t0 = cmul(f0, make_float2(a.x, a.y));
            float2 t1 = cmul(f1, make_float2(a.z, a.w));
            s0.x += t0.x; s0.y += t0.y;
            s1.x += t1.x; s1.y += t1.y;
            f0 = cmul(f0, l640);
            f1 = cmul(f1, l641);
        }
    }
    const float2* bu = (const float2*)g_Bu;
    size_t mbase = (size_t)(c * T_CHK) * B_TOT + b;
#pragma unroll 4
    for (int t = 0; t < T_CHK; t++) {
        size_t m = mbase + (size_t)t * B_TOT;
        float4 x = *(const float4*)&bu[m * 256 + p2];
        s0 = cmul(lam0, s0);
        s0.x += x.x; s0.y += x.y;
        s1 = cmul(lam1, s1);
        s1.x += x.z; s1.y += x.w;
        __nv_bfloat162 h0, l0, h1, l1;
        split_bf16(s0.x, h0.x, l0.x);
        split_bf16(s0.y, h0.y, l0.y);
        split_bf16(s1.x, h1.x, l1.x);
        split_bf16(s1.y, h1.y, l1.y);
        *(uint2*)&g_ohw[m * 256 + p2] = make_uint2(*(uint32_t*)&h0, *(uint32_t*)&h1);
        *(uint2*)&g_olw[m * 256 + p2] = make_uint2(*(uint32_t*)&l0, *(uint32_t*)&l1);
    }
}

// ---------------- GEMM2: out = o @ W2 + D*u (M=65536, N=128, K=512; 16 kt) ----------------
__global__ __launch_bounds__(256, 2) void gemm2_mma(const float* __restrict__ u,
                                                    const float* __restrict__ Dv,
                                                    float* __restrict__ out) {
    extern __shared__ char smem[];
    uint32_t sb = smem_u32(smem);
    int tid = threadIdx.x, lane = tid & 31, wid = tid >> 5;
    int gq = lane >> 2, tig = lane & 3;
    int wm = wid >> 1, wn = wid & 1;
    int bm = blockIdx.x * 128;

    float acc[2][8][4];
#pragma unroll
    for (int mt = 0; mt < 2; mt++)
#pragma unroll
        for (int nt = 0; nt < 8; nt++)
#pragma unroll
            for (int i = 0; i < 4; i++) acc[mt][nt][i] = 0.f;

#pragma unroll
    for (int i = 0; i < 2; i++) {
        int idx = tid + i * 256;
        int row = idx >> 2, seg = idx & 3;
        CP_ASYNC16(sb + OF_AH + row * 80 + seg * 16, g_ohw + (size_t)(bm + row) * 256 + seg * 4);
        CP_ASYNC16(sb + OF_AL + row * 80 + seg * 16, g_olw + (size_t)(bm + row) * 256 + seg * 4);
        CP_ASYNC16(sb + OF_BH + row * 80 + seg * 16, g_W2h + (size_t)row * 512 + seg * 8);
        CP_ASYNC16(sb + OF_BL + row * 80 + seg * 16, g_W2l + (size_t)row * 512 + seg * 8);
    }
    CP_COMMIT();

    for (int kt = 0; kt < 16; kt++) {
        int b = kt & 1;
        CP_WAIT0();
        __syncthreads();
        if (kt < 15) {
            uint32_t nb = sb + (b ^ 1) * BUF_B;
            int kn = kt + 1;
#pragma unroll
            for (int i = 0; i < 2; i++) {
                int idx = tid + i * 256;
                int row = idx >> 2, seg = idx & 3;
                CP_ASYNC16(nb + OF_AH + row * 80 + seg * 16,
                           g_ohw + (size_t)(bm + row) * 256 + kn * 16 + seg * 4);
                CP_ASYNC16(nb + OF_AL + row * 80 + seg * 16,
                           g_olw + (size_t)(bm + row) * 256 + kn * 16 + seg * 4);
                CP_ASYNC16(nb + OF_BH + row * 80 + seg * 16,
                           g_W2h + (size_t)row * 512 + kn * 32 + seg * 8);
                CP_ASYNC16(nb + OF_BL + row * 80 + seg * 16,
                           g_W2l + (size_t)row * 512 + kn * 32 + seg * 8);
            }
            CP_COMMIT();
        }
        mma_chunk(sb + b * BUF_B, wm, wn, lane, acc);
    }
#pragma unroll
    for (int mt = 0; mt < 2; mt++)
#pragma unroll
        for (int nt = 0; nt < 8; nt++) {
            int c = wn * 64 + nt * 8 + 2 * tig;
            float2 dv = *(const float2*)(Dv + c);
#pragma unroll
            for (int half = 0; half < 2; half++) {
                int r = bm + wm * 32 + mt * 16 + gq + half * 8;
                float2 uv = *(const float2*)(u + (size_t)r * 128 + c);
                float2 o;
                o.x = acc[mt][nt][2 * half + 0] + dv.x * uv.x;
                o.y = acc[mt][nt][2 * half + 1] + dv.y * uv.y;
                *(float2*)&out[(size_t)r * 128 + c] = o;
            }
        }
}

// ---------------- launch ----------------
extern "C" void kernel_launch(void* const* d_in, const int* in_sizes, int n_in,
                              void* d_out, int out_size) {
    const float* u   = (const float*)d_in[0];
    const float* lLr = (const float*)d_in[1];
    const float* Li  = (const float*)d_in[2];
    const float* Br  = (const float*)d_in[3];
    const float* Bi  = (const float*)d_in[4];
    const float* Cr  = (const float*)d_in[5];
    const float* Ci  = (const float*)d_in[6];
    const float* Dv  = (const float*)d_in[7];
    const float* lDt = (const float*)d_in[8];
    float* out = (float*)d_out;

    cudaFuncSetAttribute(gemm1_mma, cudaFuncAttributeMaxDynamicSharedMemorySize, SMEM_TOTAL);
    cudaFuncSetAttribute(gemm2_mma, cudaFuncAttributeMaxDynamicSharedMemorySize, SMEM_TOTAL);

    precompute_a<<<1, 256>>>(lLr, Li, lDt);
    precompute_w<<<128, 256>>>(Br, Bi, Cr, Ci);

    gemm1_mma<<<dim3(4, M_TOT / 128), 256, SMEM_TOTAL>>>(u);

    scan_local_kernel<<<C_CHK * 16, 256>>>();
    scan_final_kernel<<<C_CHK * 16, 256>>>();

    gemm2_mma<<<M_TOT / 128, 256, SMEM_TOTAL>>>(u, Dv, out);
}

// round 15
// speedup vs baseline: 3.9179x; 1.2060x over previous
#include <cuda_runtime.h>
#include <cuda_fp16.h>
#include <math.h>
#include <stdint.h>

// ---------------- problem constants ----------------
#define L_TOT 2048
#define B_TOT 32
#define H_TOT 128
#define P_TOT 256
#define T_CHK 64
#define C_CHK (L_TOT / T_CHK)       // 32 chunks
#define M_TOT (L_TOT * B_TOT)       // 65536 rows
#define NB2   512                   // Bu width in real floats (2*P)

// ---------------- scratch (device globals) ----------------
__device__ float    g_Bu[(size_t)M_TOT * NB2];     // 134 MB fp32 Bu -> consumed by scan
__device__ uint32_t g_ohw[(size_t)M_TOT * 256];    // o hi: fp16x2 words [m][256]
__device__ uint32_t g_olw[(size_t)M_TOT * 256];    // o lo
__device__ float2 g_Sloc[C_CHK * B_TOT * P_TOT];   // per-chunk local aggregates
__device__ float2 g_Lam[P_TOT];
__device__ float2 g_LamT[P_TOT];
__device__ float2 g_coeff[P_TOT];
// weights: single fp16 hi plane, n-major [n][k]
__device__ __half g_W1h[512 * 128];
__device__ __half g_W2h[128 * 512];

// ---------------- helpers ----------------
__device__ __forceinline__ void split_fp16(float v, __half& h, __half& l) {
    h = __float2half_rn(v);
    l = __float2half_rn(v - __half2float(h));
}
__device__ __forceinline__ float2 cmul(float2 a, float2 b) {
    return make_float2(a.x * b.x - a.y * b.y, a.x * b.y + a.y * b.x);
}
__device__ __forceinline__ void mma16816(float* d, const uint32_t* a, const uint32_t* b) {
    asm volatile(
        "mma.sync.aligned.m16n8k16.row.col.f32.f16.f16.f32 "
        "{%0,%1,%2,%3}, {%4,%5,%6,%7}, {%8,%9}, {%0,%1,%2,%3};"
        : "+f"(d[0]), "+f"(d[1]), "+f"(d[2]), "+f"(d[3])
        : "r"(a[0]), "r"(a[1]), "r"(a[2]), "r"(a[3]), "r"(b[0]), "r"(b[1]));
}
__device__ __forceinline__ void ldsm4(uint32_t& r0, uint32_t& r1, uint32_t& r2, uint32_t& r3,
                                      uint32_t addr) {
    asm volatile("ldmatrix.sync.aligned.m8n8.x4.shared.b16 {%0,%1,%2,%3}, [%4];"
                 : "=r"(r0), "=r"(r1), "=r"(r2), "=r"(r3) : "r"(addr));
}
__device__ __forceinline__ uint32_t smem_u32(const void* p) {
    uint32_t a;
    asm("{ .reg .u64 t; cvta.to.shared.u64 t, %1; cvt.u32.u64 %0, t; }" : "=r"(a) : "l"(p));
    return a;
}
#define CP_ASYNC16(dst, src) \
    asm volatile("cp.async.cg.shared.global [%0], [%1], 16;" :: "r"(dst), "l"(src))
#define CP_COMMIT() asm volatile("cp.async.commit_group;" ::: "memory")
#define CP_WAIT0()  asm volatile("cp.async.wait_group 0;" ::: "memory")

// SMEM tile geometry: rows of 40 fp16 (80 B stride), 128 rows/tile
#define TILE_B (128 * 40 * 2)      // 10240 B
#define OF_AH 0
#define OF_AL TILE_B
#define OF_BH (2 * TILE_B)
#define BUF_B (3 * TILE_B)         // 30720 B per stage
#define SMEM_TOTAL (2 * BUF_B)     // 61440 B

// ---------------- K0a: per-p scalar precompute ----------------
__global__ void precompute_a(const float* __restrict__ lLr, const float* __restrict__ Li,
                             const float* __restrict__ lDelta) {
    int p = threadIdx.x;
    double lamr = -exp((double)lLr[p]);
    double lami = (double)Li[p];
    double dt = exp((double)lDelta[p]);
    double lbr = lamr * dt, lbi = lami * dt;
    double er = exp(lbr);
    double Lr = er * cos(lbi), Limg = er * sin(lbi);
    g_Lam[p] = make_float2((float)Lr, (float)Limg);
    double eT = exp((double)T_CHK * lbr);
    g_LamT[p] = make_float2((float)(eT * cos((double)T_CHK * lbi)),
                            (float)(eT * sin((double)T_CHK * lbi)));
    double nr = Lr - 1.0, ni = Limg;
    double den = lamr * lamr + lami * lami;
    g_coeff[p] = make_float2((float)((nr * lamr + ni * lami) / den),
                             (float)((ni * lamr - nr * lami) / den));
}

// ---------------- K0b: pack weights into fp16 hi plane ----------------
__global__ __launch_bounds__(256) void precompute_w(
    const float* __restrict__ Br, const float* __restrict__ Bi,
    const float* __restrict__ Cr, const float* __restrict__ Ci) {
    int idx = blockIdx.x * 256 + threadIdx.x;  // 32768 = 128 h x 256 p
    int h = idx >> 8, p = idx & 255;
    float2 cf = g_coeff[p];
    float br = Br[p * H_TOT + h], bi = Bi[p * H_TOT + h];
    float w1v[2] = {cf.x * br - cf.y * bi, cf.x * bi + cf.y * br};
#pragma unroll
    for (int j = 0; j < 2; j++) {
        int n = 2 * p + j;
        g_W1h[(size_t)n * 128 + h] = __float2half_rn(w1v[j]);
    }
    float w2v[2] = {Cr[h * P_TOT + p], -Ci[h * P_TOT + p]};
#pragma unroll
    for (int j = 0; j < 2; j++) {
        int k = 2 * p + j;
        g_W2h[(size_t)h * 512 + k] = __float2half_rn(w2v[j]);
    }
}

// ---------------- shared MMA inner step (fp16 2-pass) ----------------
// acc += Ah*Bh + Al*Bh over one 32-wide K chunk at smem u32 base `sbuf`
__device__ __forceinline__ void mma_chunk(uint32_t sbuf, int wm, int wn, int lane,
                                          float acc[2][8][4]) {
    int g = lane >> 3, rg = lane & 7;
#pragma unroll
    for (int kk = 0; kk < 2; kk++) {
        int k16 = kk * 16;
        uint32_t ah[2][4], al[2][4];
#pragma unroll
        for (int mt = 0; mt < 2; mt++) {
            int row = wm * 32 + mt * 16 + (g & 1) * 8 + rg;
            int col = k16 + (g >> 1) * 8;
            uint32_t a = sbuf + row * 80 + col * 2;
            ldsm4(ah[mt][0], ah[mt][1], ah[mt][2], ah[mt][3], a + OF_AH);
            ldsm4(al[mt][0], al[mt][1], al[mt][2], al[mt][3], a + OF_AL);
        }
        uint32_t b[8][2];
        {
            int row = wn * 64 + (g >> 1) * 8 + rg;
            int col = k16 + (g & 1) * 8;
#pragma unroll
            for (int np = 0; np < 4; np++) {
                uint32_t ba = sbuf + OF_BH + (row + np * 16) * 80 + col * 2;
                ldsm4(b[2 * np][0], b[2 * np][1], b[2 * np + 1][0], b[2 * np + 1][1], ba);
            }
#pragma unroll
            for (int mt = 0; mt < 2; mt++)
#pragma unroll
                for (int nt = 0; nt < 8; nt++) {
                    mma16816(acc[mt][nt], ah[mt], b[nt]);
                    mma16816(acc[mt][nt], al[mt], b[nt]);
                }
        }
    }
}

// ---------------- GEMM1: Bu = u @ W1 (M=65536, N=512, K=128; 4 kt) ----------------
__global__ __launch_bounds__(256, 2) void gemm1_mma(const float* __restrict__ u) {
    extern __shared__ char smem[];
    uint32_t sb = smem_u32(smem);
    int tid = threadIdx.x, lane = tid & 31, wid = tid >> 5;
    int gq = lane >> 2, tig = lane & 3;
    int wm = wid >> 1, wn = wid & 1;
    int bn = blockIdx.x * 128, bm = blockIdx.y * 128;

    float acc[2][8][4];
#pragma unroll
    for (int mt = 0; mt < 2; mt++)
#pragma unroll
        for (int nt = 0; nt < 8; nt++)
#pragma unroll
            for (int i = 0; i < 4; i++) acc[mt][nt][i] = 0.f;

    float4 areg[4];
#pragma unroll
    for (int i = 0; i < 4; i++) {
        int idx = tid + i * 256;
        int row = idx >> 3, c4 = (idx & 7) * 4;
        areg[i] = *(const float4*)(u + (size_t)(bm + row) * 128 + 0 + c4);
    }
#pragma unroll
    for (int i = 0; i < 2; i++) {
        int idx = tid + i * 256;
        int row = idx >> 2, seg = idx & 3;
        CP_ASYNC16(sb + OF_BH + row * 80 + seg * 16,
                   g_W1h + (size_t)(bn + row) * 128 + seg * 8);
    }
    CP_COMMIT();

    for (int kt = 0; kt < 4; kt++) {
        int b = kt & 1;
        char* buf = smem + b * BUF_B;
#pragma unroll
        for (int i = 0; i < 4; i++) {
            int idx = tid + i * 256;
            int row = idx >> 3, c4 = (idx & 7) * 4;
            float4 v = areg[i];
            __half h0, h1, h2, h3, l0, l1, l2, l3;
            split_fp16(v.x, h0, l0);
            split_fp16(v.y, h1, l1);
            split_fp16(v.z, h2, l2);
            split_fp16(v.w, h3, l3);
            __half2 h01 = __halves2half2(h0, h1), h23 = __halves2half2(h2, h3);
            __half2 l01 = __halves2half2(l0, l1), l23 = __halves2half2(l2, l3);
            *(uint2*)(buf + OF_AH + row * 80 + c4 * 2) =
                make_uint2(*(uint32_t*)&h01, *(uint32_t*)&h23);
            *(uint2*)(buf + OF_AL + row * 80 + c4 * 2) =
                make_uint2(*(uint32_t*)&l01, *(uint32_t*)&l23);
        }
        if (kt < 3) {
#pragma unroll
            for (int i = 0; i < 4; i++) {
                int idx = tid + i * 256;
                int row = idx >> 3, c4 = (idx & 7) * 4;
                areg[i] = *(const float4*)(u + (size_t)(bm + row) * 128 + (kt + 1) * 32 + c4);
            }
        }
        CP_WAIT0();
        __syncthreads();
        if (kt < 3) {
            uint32_t nb = sb + (b ^ 1) * BUF_B;
#pragma unroll
            for (int i = 0; i < 2; i++) {
                int idx = tid + i * 256;
                int row = idx >> 2, seg = idx & 3;
                CP_ASYNC16(nb + OF_BH + row * 80 + seg * 16,
                           g_W1h + (size_t)(bn + row) * 128 + (kt + 1) * 32 + seg * 8);
            }
            CP_COMMIT();
        }
        mma_chunk(sb + b * BUF_B, wm, wn, lane, acc);
    }
#pragma unroll
    for (int mt = 0; mt < 2; mt++)
#pragma unroll
        for (int nt = 0; nt < 8; nt++) {
            int r = bm + wm * 32 + mt * 16 + gq;
            int c = bn + wn * 64 + nt * 8 + 2 * tig;
            *(float2*)&g_Bu[(size_t)r * NB2 + c] = make_float2(acc[mt][nt][0], acc[mt][nt][1]);
            *(float2*)&g_Bu[(size_t)(r + 8) * NB2 + c] = make_float2(acc[mt][nt][2], acc[mt][nt][3]);
        }
}

// ---------------- K2: per-chunk local scan (aggregates only) ----------------
__global__ __launch_bounds__(256) void scan_local_kernel() {
    int p = threadIdx.x;
    int b = blockIdx.x % B_TOT;
    int c = blockIdx.x / B_TOT;
    float2 lam = g_Lam[p];
    float2 s = make_float2(0.f, 0.f);
    const float2* base = (const float2*)g_Bu + ((size_t)(c * T_CHK) * B_TOT + b) * P_TOT + p;
    const size_t stride = (size_t)B_TOT * P_TOT;
#pragma unroll 8
    for (int t = 0; t < T_CHK; t++) {
        float2 x = base[t * stride];
        s = cmul(lam, s);
        s.x += x.x; s.y += x.y;
    }
    g_Sloc[((size_t)c * B_TOT + b) * P_TOT + p] = s;
}

// ---------------- K3: final scan with inline prefix, emit fp16 hi/lo ----------------
__global__ __launch_bounds__(256) void scan_final_kernel() {
    int p = threadIdx.x;
    int b = blockIdx.x % B_TOT;
    int c = blockIdx.x / B_TOT;
    float2 lam = g_Lam[p];
    float2 s = make_float2(0.f, 0.f);
    {
        float2 lam64 = g_LamT[p];
        float2 f = make_float2(1.f, 0.f);
        for (int j = c - 1; j >= 0; j--) {
            float2 a = g_Sloc[((size_t)j * B_TOT + b) * P_TOT + p];
            float2 t = cmul(f, a);
            s.x += t.x; s.y += t.y;
            f = cmul(f, lam64);
        }
    }
    const float2* base = (const float2*)g_Bu + ((size_t)(c * T_CHK) * B_TOT + b) * P_TOT + p;
    const size_t stride = (size_t)B_TOT * P_TOT;
    size_t mbase = (size_t)(c * T_CHK) * B_TOT + b;
#pragma unroll 8
    for (int t = 0; t < T_CHK; t++) {
        float2 x = base[t * stride];
        s = cmul(lam, s);
        s.x += x.x; s.y += x.y;
        size_t m = mbase + (size_t)t * B_TOT;
        __half hx, lx, hy, ly;
        split_fp16(s.x, hx, lx);
        split_fp16(s.y, hy, ly);
        __half2 hh = __halves2half2(hx, hy), ll = __halves2half2(lx, ly);
        g_ohw[m * 256 + p] = *(uint32_t*)&hh;
        g_olw[m * 256 + p] = *(uint32_t*)&ll;
    }
}

// ---------------- GEMM2: out = o @ W2 + D*u (M=65536, N=128, K=512; 16 kt) ----------------
__global__ __launch_bounds__(256, 2) void gemm2_mma(const float* __restrict__ u,
                                                    const float* __restrict__ Dv,
                                                    float* __restrict__ out) {
    extern __shared__ char smem[];
    uint32_t sb = smem_u32(smem);
    int tid = threadIdx.x, lane = tid & 31, wid = tid >> 5;
    int gq = lane >> 2, tig = lane & 3;
    int wm = wid >> 1, wn = wid & 1;
    int bm = blockIdx.x * 128;

    float acc[2][8][4];
#pragma unroll
    for (int mt = 0; mt < 2; mt++)
#pragma unroll
        for (int nt = 0; nt < 8; nt++)
#pragma unroll
            for (int i = 0; i < 4; i++) acc[mt][nt][i] = 0.f;

#pragma unroll
    for (int i = 0; i < 2; i++) {
        int idx = tid + i * 256;
        int row = idx >> 2, seg = idx & 3;
        CP_ASYNC16(sb + OF_AH + row * 80 + seg * 16, g_ohw + (size_t)(bm + row) * 256 + seg * 4);
        CP_ASYNC16(sb + OF_AL + row * 80 + seg * 16, g_olw + (size_t)(bm + row) * 256 + seg * 4);
        CP_ASYNC16(sb + OF_BH + row * 80 + seg * 16, g_W2h + (size_t)row * 512 + seg * 8);
    }
    CP_COMMIT();

    for (int kt = 0; kt < 16; kt++) {
        int b = kt & 1;
        CP_WAIT0();
        __syncthreads();
        if (kt < 15) {
            uint32_t nb = sb + (b ^ 1) * BUF_B;
            int kn = kt + 1;
#pragma unroll
            for (int i = 0; i < 2; i++) {
                int idx = tid + i * 256;
                int row = idx >> 2, seg = idx & 3;
                CP_ASYNC16(nb + OF_AH + row * 80 + seg * 16,
                           g_ohw + (size_t)(bm + row) * 256 + kn * 16 + seg * 4);
                CP_ASYNC16(nb + OF_AL + row * 80 + seg * 16,
                           g_olw + (size_t)(bm + row) * 256 + kn * 16 + seg * 4);
                CP_ASYNC16(nb + OF_BH + row * 80 + seg * 16,
                           g_W2h + (size_t)row * 512 + kn * 32 + seg * 8);
            }
            CP_COMMIT();
        }
        mma_chunk(sb + b * BUF_B, wm, wn, lane, acc);
    }
#pragma unroll
    for (int mt = 0; mt < 2; mt++)
#pragma unroll
        for (int nt = 0; nt < 8; nt++) {
            int c = wn * 64 + nt * 8 + 2 * tig;
            float2 dv = *(const float2*)(Dv + c);
#pragma unroll
            for (int half = 0; half < 2; half++) {
                int r = bm + wm * 32 + mt * 16 + gq + half * 8;
                float2 uv = *(const float2*)(u + (size_t)r * 128 + c);
                float2 o;
                o.x = acc[mt][nt][2 * half + 0] + dv.x * uv.x;
                o.y = acc[mt][nt][2 * half + 1] + dv.y * uv.y;
                *(float2*)&out[(size_t)r * 128 + c] = o;
            }
        }
}

// ---------------- launch ----------------
extern "C" void kernel_launch(void* const* d_in, const int* in_sizes, int n_in,
                              void* d_out, int out_size) {
    const float* u   = (const float*)d_in[0];
    const float* lLr = (const float*)d_in[1];
    const float* Li  = (const float*)d_in[2];
    const float* Br  = (const float*)d_in[3];
    const float* Bi  = (const float*)d_in[4];
    const float* Cr  = (const float*)d_in[5];
    const float* Ci  = (const float*)d_in[6];
    const float* Dv  = (const float*)d_in[7];
    const float* lDt = (const float*)d_in[8];
    float* out = (float*)d_out;

    cudaFuncSetAttribute(gemm1_mma, cudaFuncAttributeMaxDynamicSharedMemorySize, SMEM_TOTAL);
    cudaFuncSetAttribute(gemm2_mma, cudaFuncAttributeMaxDynamicSharedMemorySize, SMEM_TOTAL);

    precompute_a<<<1, 256>>>(lLr, Li, lDt);
    precompute_w<<<128, 256>>>(Br, Bi, Cr, Ci);

    gemm1_mma<<<dim3(4, M_TOT / 128), 256, SMEM_TOTAL>>>(u);

    scan_local_kernel<<<C_CHK * B_TOT, 256>>>();
    scan_final_kernel<<<C_CHK * B_TOT, 256>>>();

    gemm2_mma<<<M_TOT / 128, 256, SMEM_TOTAL>>>(u, Dv, out);
}

// round 16
// speedup vs baseline: 4.6940x; 1.1981x over previous
#include <cuda_runtime.h>
#include <cuda_fp16.h>
#include <math.h>
#include <stdint.h>

// ---------------- problem constants ----------------
#define L_TOT 2048
#define B_TOT 32
#define H_TOT 128
#define P_TOT 256
#define T_CHK 64
#define C_CHK (L_TOT / T_CHK)       // 32 chunks
#define M_TOT (L_TOT * B_TOT)       // 65536 rows
#define NB2   512                   // Bu width in real floats (2*P)

// ---------------- scratch (device globals) ----------------
__device__ float    g_Bu[(size_t)M_TOT * NB2];     // 134 MB fp32 Bu -> consumed by scan
__device__ uint32_t g_ohw[(size_t)M_TOT * 256];    // o: fp16x2 words [m][256]
__device__ float2 g_Sloc[C_CHK * B_TOT * P_TOT];   // per-chunk local aggregates
__device__ float2 g_Lam[P_TOT];
__device__ float2 g_LamT[P_TOT];
__device__ float2 g_coeff[P_TOT];
// weights: single fp16 plane, n-major [n][k]
__device__ __half g_W1h[512 * 128];
__device__ __half g_W2h[128 * 512];

// ---------------- helpers ----------------
__device__ __forceinline__ float2 cmul(float2 a, float2 b) {
    return make_float2(a.x * b.x - a.y * b.y, a.x * b.y + a.y * b.x);
}
__device__ __forceinline__ void mma16816(float* d, const uint32_t* a, const uint32_t* b) {
    asm volatile(
        "mma.sync.aligned.m16n8k16.row.col.f32.f16.f16.f32 "
        "{%0,%1,%2,%3}, {%4,%5,%6,%7}, {%8,%9}, {%0,%1,%2,%3};"
        : "+f"(d[0]), "+f"(d[1]), "+f"(d[2]), "+f"(d[3])
        : "r"(a[0]), "r"(a[1]), "r"(a[2]), "r"(a[3]), "r"(b[0]), "r"(b[1]));
}
__device__ __forceinline__ void ldsm4(uint32_t& r0, uint32_t& r1, uint32_t& r2, uint32_t& r3,
                                      uint32_t addr) {
    asm volatile("ldmatrix.sync.aligned.m8n8.x4.shared.b16 {%0,%1,%2,%3}, [%4];"
                 : "=r"(r0), "=r"(r1), "=r"(r2), "=r"(r3) : "r"(addr));
}
__device__ __forceinline__ uint32_t smem_u32(const void* p) {
    uint32_t a;
    asm("{ .reg .u64 t; cvta.to.shared.u64 t, %1; cvt.u32.u64 %0, t; }" : "=r"(a) : "l"(p));
    return a;
}
#define CP_ASYNC16(dst, src) \
    asm volatile("cp.async.cg.shared.global [%0], [%1], 16;" :: "r"(dst), "l"(src))
#define CP_COMMIT() asm volatile("cp.async.commit_group;" ::: "memory")
#define CP_WAIT0()  asm volatile("cp.async.wait_group 0;" ::: "memory")

// SMEM tile geometry: rows of 40 fp16 (80 B stride), 128 rows/tile
#define TILE_B (128 * 40 * 2)      // 10240 B
#define OF_A 0
#define OF_B TILE_B
#define BUF_B (2 * TILE_B)         // 20480 B per stage
#define SMEM_TOTAL (2 * BUF_B)     // 40960 B

// ---------------- K0a: per-p scalar precompute ----------------
__global__ void precompute_a(const float* __restrict__ lLr, const float* __restrict__ Li,
                             const float* __restrict__ lDelta) {
    int p = threadIdx.x;
    double lamr = -exp((double)lLr[p]);
    double lami = (double)Li[p];
    double dt = exp((double)lDelta[p]);
    double lbr = lamr * dt, lbi = lami * dt;
    double er = exp(lbr);
    double Lr = er * cos(lbi), Limg = er * sin(lbi);
    g_Lam[p] = make_float2((float)Lr, (float)Limg);
    double eT = exp((double)T_CHK * lbr);
    g_LamT[p] = make_float2((float)(eT * cos((double)T_CHK * lbi)),
                            (float)(eT * sin((double)T_CHK * lbi)));
    double nr = Lr - 1.0, ni = Limg;
    double den = lamr * lamr + lami * lami;
    g_coeff[p] = make_float2((float)((nr * lamr + ni * lami) / den),
                             (float)((ni * lamr - nr * lami) / den));
}

// ---------------- K0b: pack weights into fp16 plane ----------------
__global__ __launch_bounds__(256) void precompute_w(
    const float* __restrict__ Br, const float* __restrict__ Bi,
    const float* __restrict__ Cr, const float* __restrict__ Ci) {
    int idx = blockIdx.x * 256 + threadIdx.x;  // 32768 = 128 h x 256 p
    int h = idx >> 8, p = idx & 255;
    float2 cf = g_coeff[p];
    float br = Br[p * H_TOT + h], bi = Bi[p * H_TOT + h];
    float w1v[2] = {cf.x * br - cf.y * bi, cf.x * bi + cf.y * br};
#pragma unroll
    for (int j = 0; j < 2; j++) {
        int n = 2 * p + j;
        g_W1h[(size_t)n * 128 + h] = __float2half_rn(w1v[j]);
    }
    float w2v[2] = {Cr[h * P_TOT + p], -Ci[h * P_TOT + p]};
#pragma unroll
    for (int j = 0; j < 2; j++) {
        int k = 2 * p + j;
        g_W2h[(size_t)h * 512 + k] = __float2half_rn(w2v[j]);
    }
}

// ---------------- shared MMA inner step (fp16 single-pass) ----------------
// acc += A*B over one 32-wide K chunk at smem u32 base `sbuf`
__device__ __forceinline__ void mma_chunk(uint32_t sbuf, int wm, int wn, int lane,
                                          float acc[2][8][4]) {
    int g = lane >> 3, rg = lane & 7;
#pragma unroll
    for (int kk = 0; kk < 2; kk++) {
        int k16 = kk * 16;
        uint32_t ah[2][4];
#pragma unroll
        for (int mt = 0; mt < 2; mt++) {
            int row = wm * 32 + mt * 16 + (g & 1) * 8 + rg;
            int col = k16 + (g >> 1) * 8;
            uint32_t a = sbuf + OF_A + row * 80 + col * 2;
            ldsm4(ah[mt][0], ah[mt][1], ah[mt][2], ah[mt][3], a);
        }
        uint32_t b[8][2];
        {
            int row = wn * 64 + (g >> 1) * 8 + rg;
            int col = k16 + (g & 1) * 8;
#pragma unroll
            for (int np = 0; np < 4; np++) {
                uint32_t ba = sbuf + OF_B + (row + np * 16) * 80 + col * 2;
                ldsm4(b[2 * np][0], b[2 * np][1], b[2 * np + 1][0], b[2 * np + 1][1], ba);
            }
#pragma unroll
            for (int mt = 0; mt < 2; mt++)
#pragma unroll
                for (int nt = 0; nt < 8; nt++)
                    mma16816(acc[mt][nt], ah[mt], b[nt]);
        }
    }
}

// ---------------- GEMM1: Bu = u @ W1 (M=65536, N=512, K=128; 4 kt) ----------------
__global__ __launch_bounds__(256, 2) void gemm1_mma(const float* __restrict__ u) {
    extern __shared__ char smem[];
    uint32_t sb = smem_u32(smem);
    int tid = threadIdx.x, lane = tid & 31, wid = tid >> 5;
    int gq = lane >> 2, tig = lane & 3;
    int wm = wid >> 1, wn = wid & 1;
    int bn = blockIdx.x * 128, bm = blockIdx.y * 128;

    float acc[2][8][4];
#pragma unroll
    for (int mt = 0; mt < 2; mt++)
#pragma unroll
        for (int nt = 0; nt < 8; nt++)
#pragma unroll
            for (int i = 0; i < 4; i++) acc[mt][nt][i] = 0.f;

    float4 areg[4];
#pragma unroll
    for (int i = 0; i < 4; i++) {
        int idx = tid + i * 256;
        int row = idx >> 3, c4 = (idx & 7) * 4;
        areg[i] = *(const float4*)(u + (size_t)(bm + row) * 128 + 0 + c4);
    }
#pragma unroll
    for (int i = 0; i < 2; i++) {
        int idx = tid + i * 256;
        int row = idx >> 2, seg = idx & 3;
        CP_ASYNC16(sb + OF_B + row * 80 + seg * 16,
                   g_W1h + (size_t)(bn + row) * 128 + seg * 8);
    }
    CP_COMMIT();

    for (int kt = 0; kt < 4; kt++) {
        int b = kt & 1;
        char* buf = smem + b * BUF_B;
#pragma unroll
        for (int i = 0; i < 4; i++) {
            int idx = tid + i * 256;
            int row = idx >> 3, c4 = (idx & 7) * 4;
            float4 v = areg[i];
            __half2 h01 = __halves2half2(__float2half_rn(v.x), __float2half_rn(v.y));
            __half2 h23 = __halves2half2(__float2half_rn(v.z), __float2half_rn(v.w));
            *(uint2*)(buf + OF_A + row * 80 + c4 * 2) =
                make_uint2(*(uint32_t*)&h01, *(uint32_t*)&h23);
        }
        if (kt < 3) {
#pragma unroll
            for (int i = 0; i < 4; i++) {
                int idx = tid + i * 256;
                int row = idx >> 3, c4 = (idx & 7) * 4;
                areg[i] = *(const float4*)(u + (size_t)(bm + row) * 128 + (kt + 1) * 32 + c4);
            }
        }
        CP_WAIT0();
        __syncthreads();
        if (kt < 3) {
            uint32_t nb = sb + (b ^ 1) * BUF_B;
#pragma unroll
            for (int i = 0; i < 2; i++) {
                int idx = tid + i * 256;
                int row = idx >> 2, seg = idx & 3;
                CP_ASYNC16(nb + OF_B + row * 80 + seg * 16,
                           g_W1h + (size_t)(bn + row) * 128 + (kt + 1) * 32 + seg * 8);
            }
            CP_COMMIT();
        }
        mma_chunk(sb + b * BUF_B, wm, wn, lane, acc);
    }
#pragma unroll
    for (int mt = 0; mt < 2; mt++)
#pragma unroll
        for (int nt = 0; nt < 8; nt++) {
            int r = bm + wm * 32 + mt * 16 + gq;
            int c = bn + wn * 64 + nt * 8 + 2 * tig;
            *(float2*)&g_Bu[(size_t)r * NB2 + c] = make_float2(acc[mt][nt][0], acc[mt][nt][1]);
            *(float2*)&g_Bu[(size_t)(r + 8) * NB2 + c] = make_float2(acc[mt][nt][2], acc[mt][nt][3]);
        }
}

// ---------------- K2: per-chunk local scan (aggregates only) ----------------
__global__ __launch_bounds__(256) void scan_local_kernel() {
    int p = threadIdx.x;
    int b = blockIdx.x % B_TOT;
    int c = blockIdx.x / B_TOT;
    float2 lam = g_Lam[p];
    float2 s = make_float2(0.f, 0.f);
    const float2* base = (const float2*)g_Bu + ((size_t)(c * T_CHK) * B_TOT + b) * P_TOT + p;
    const size_t stride = (size_t)B_TOT * P_TOT;
#pragma unroll 8
    for (int t = 0; t < T_CHK; t++) {
        float2 x = base[t * stride];
        s = cmul(lam, s);
        s.x += x.x; s.y += x.y;
    }
    g_Sloc[((size_t)c * B_TOT + b) * P_TOT + p] = s;
}

// ---------------- K3: final scan with inline prefix, emit fp16 words ----------------
__global__ __launch_bounds__(256) void scan_final_kernel() {
    int p = threadIdx.x;
    int b = blockIdx.x % B_TOT;
    int c = blockIdx.x / B_TOT;
    float2 lam = g_Lam[p];
    float2 s = make_float2(0.f, 0.f);
    {
        float2 lam64 = g_LamT[p];
        float2 f = make_float2(1.f, 0.f);
        for (int j = c - 1; j >= 0; j--) {
            float2 a = g_Sloc[((size_t)j * B_TOT + b) * P_TOT + p];
            float2 t = cmul(f, a);
            s.x += t.x; s.y += t.y;
            f = cmul(f, lam64);
        }
    }
    const float2* base = (const float2*)g_Bu + ((size_t)(c * T_CHK) * B_TOT + b) * P_TOT + p;
    const size_t stride = (size_t)B_TOT * P_TOT;
    size_t mbase = (size_t)(c * T_CHK) * B_TOT + b;
#pragma unroll 8
    for (int t = 0; t < T_CHK; t++) {
        float2 x = base[t * stride];
        s = cmul(lam, s);
        s.x += x.x; s.y += x.y;
        size_t m = mbase + (size_t)t * B_TOT;
        __half2 hh = __halves2half2(__float2half_rn(s.x), __float2half_rn(s.y));
        g_ohw[m * 256 + p] = *(uint32_t*)&hh;
    }
}

// ---------------- GEMM2: out = o @ W2 + D*u (M=65536, N=128, K=512; 16 kt) ----------------
__global__ __launch_bounds__(256, 2) void gemm2_mma(const float* __restrict__ u,
                                                    const float* __restrict__ Dv,
                                                    float* __restrict__ out) {
    extern __shared__ char smem[];
    uint32_t sb = smem_u32(smem);
    int tid = threadIdx.x, lane = tid & 31, wid = tid >> 5;
    int gq = lane >> 2, tig = lane & 3;
    int wm = wid >> 1, wn = wid & 1;
    int bm = blockIdx.x * 128;

    float acc[2][8][4];
#pragma unroll
    for (int mt = 0; mt < 2; mt++)
#pragma unroll
        for (int nt = 0; nt < 8; nt++)
#pragma unroll
            for (int i = 0; i < 4; i++) acc[mt][nt][i] = 0.f;

#pragma unroll
    for (int i = 0; i < 2; i++) {
        int idx = tid + i * 256;
        int row = idx >> 2, seg = idx & 3;
        CP_ASYNC16(sb + OF_A + row * 80 + seg * 16, g_ohw + (size_t)(bm + row) * 256 + seg * 4);
        CP_ASYNC16(sb + OF_B + row * 80 + seg * 16, g_W2h + (size_t)row * 512 + seg * 8);
    }
    CP_COMMIT();

    for (int kt = 0; kt < 16; kt++) {
        int b = kt & 1;
        CP_WAIT0();
        __syncthreads();
        if (kt < 15) {
            uint32_t nb = sb + (b ^ 1) * BUF_B;
            int kn = kt + 1;
#pragma unroll
            for (int i = 0; i < 2; i++) {
                int idx = tid + i * 256;
                int row = idx >> 2, seg = idx & 3;
                CP_ASYNC16(nb + OF_A + row * 80 + seg * 16,
                           g_ohw + (size_t)(bm + row) * 256 + kn * 16 + seg * 4);
                CP_ASYNC16(nb + OF_B + row * 80 + seg * 16,
                           g_W2h + (size_t)row * 512 + kn * 32 + seg * 8);
            }
            CP_COMMIT();
        }
        mma_chunk(sb + b * BUF_B, wm, wn, lane, acc);
    }
#pragma unroll
    for (int mt = 0; mt < 2; mt++)
#pragma unroll
        for (int nt = 0; nt < 8; nt++) {
            int c = wn * 64 + nt * 8 + 2 * tig;
            float2 dv = *(const float2*)(Dv + c);
#pragma unroll
            for (int half = 0; half < 2; half++) {
                int r = bm + wm * 32 + mt * 16 + gq + half * 8;
                float2 uv = *(const float2*)(u + (size_t)r * 128 + c);
                float2 o;
                o.x = acc[mt][nt][2 * half + 0] + dv.x * uv.x;
                o.y = acc[mt][nt][2 * half + 1] + dv.y * uv.y;
                *(float2*)&out[(size_t)r * 128 + c] = o;
            }
        }
}

// ---------------- launch ----------------
extern "C" void kernel_launch(void* const* d_in, const int* in_sizes, int n_in,
                              void* d_out, int out_size) {
    const float* u   = (const float*)d_in[0];
    const float* lLr = (const float*)d_in[1];
    const float* Li  = (const float*)d_in[2];
    const float* Br  = (const float*)d_in[3];
    const float* Bi  = (const float*)d_in[4];
    const float* Cr  = (const float*)d_in[5];
    const float* Ci  = (const float*)d_in[6];
    const float* Dv  = (const float*)d_in[7];
    const float* lDt = (const float*)d_in[8];
    float* out = (float*)d_out;

    cudaFuncSetAttribute(gemm1_mma, cudaFuncAttributeMaxDynamicSharedMemorySize, SMEM_TOTAL);
    cudaFuncSetAttribute(gemm2_mma, cudaFuncAttributeMaxDynamicSharedMemorySize, SMEM_TOTAL);

    precompute_a<<<1, 256>>>(lLr, Li, lDt);
    precompute_w<<<128, 256>>>(Br, Bi, Cr, Ci);

    gemm1_mma<<<dim3(4, M_TOT / 128), 256, SMEM_TOTAL>>>(u);

    scan_local_kernel<<<C_CHK * B_TOT, 256>>>();
    scan_final_kernel<<<C_CHK * B_TOT, 256>>>();

    gemm2_mma<<<M_TOT / 128, 256, SMEM_TOTAL>>>(u, Dv, out);
}

// round 17
// speedup vs baseline: 5.2698x; 1.1227x over previous
#include <cuda_runtime.h>
#include <cuda_fp16.h>
#include <math.h>
#include <stdint.h>

// ---------------- problem constants ----------------
#define L_TOT 2048
#define B_TOT 32
#define H_TOT 128
#define P_TOT 256
#define T_CHK 64
#define C_CHK (L_TOT / T_CHK)       // 32 chunks
#define M_TOT (L_TOT * B_TOT)       // 65536 rows
#define NB2   512                   // Bu width in real floats (2*P)

// ---------------- scratch (device globals) ----------------
__device__ uint32_t g_Bu16[(size_t)M_TOT * 256];   // Bu as fp16x2 (re,im) words [m][256] — 67 MB
__device__ uint32_t g_ohw[(size_t)M_TOT * 256];    // o: fp16x2 words [m][256]
__device__ float2 g_Sloc[C_CHK * B_TOT * P_TOT];   // per-chunk local aggregates (fp32)
__device__ float2 g_Lam[P_TOT];
__device__ float2 g_LamT[P_TOT];
__device__ float2 g_coeff[P_TOT];
// weights: single fp16 plane, n-major [n][k]
__device__ __half g_W1h[512 * 128];
__device__ __half g_W2h[128 * 512];

// ---------------- helpers ----------------
__device__ __forceinline__ float2 cmul(float2 a, float2 b) {
    return make_float2(a.x * b.x - a.y * b.y, a.x * b.y + a.y * b.x);
}
__device__ __forceinline__ float2 unpack_h2(uint32_t w) {
    __half2 h = *(__half2*)&w;
    return make_float2(__half2float(h.x), __half2float(h.y));
}
__device__ __forceinline__ void mma16816(float* d, const uint32_t* a, const uint32_t* b) {
    asm volatile(
        "mma.sync.aligned.m16n8k16.row.col.f32.f16.f16.f32 "
        "{%0,%1,%2,%3}, {%4,%5,%6,%7}, {%8,%9}, {%0,%1,%2,%3};"
        : "+f"(d[0]), "+f"(d[1]), "+f"(d[2]), "+f"(d[3])
        : "r"(a[0]), "r"(a[1]), "r"(a[2]), "r"(a[3]), "r"(b[0]), "r"(b[1]));
}
__device__ __forceinline__ void ldsm4(uint32_t& r0, uint32_t& r1, uint32_t& r2, uint32_t& r3,
                                      uint32_t addr) {
    asm volatile("ldmatrix.sync.aligned.m8n8.x4.shared.b16 {%0,%1,%2,%3}, [%4];"
                 : "=r"(r0), "=r"(r1), "=r"(r2), "=r"(r3) : "r"(addr));
}
__device__ __forceinline__ uint32_t smem_u32(const void* p) {
    uint32_t a;
    asm("{ .reg .u64 t; cvta.to.shared.u64 t, %1; cvt.u32.u64 %0, t; }" : "=r"(a) : "l"(p));
    return a;
}
#define CP_ASYNC16(dst, src) \
    asm volatile("cp.async.cg.shared.global [%0], [%1], 16;" :: "r"(dst), "l"(src))
#define CP_COMMIT() asm volatile("cp.async.commit_group;" ::: "memory")
#define CP_WAIT0()  asm volatile("cp.async.wait_group 0;" ::: "memory")

// SMEM tile geometry: rows of 40 fp16 (80 B stride), 128 rows/tile
#define TILE_B (128 * 40 * 2)      // 10240 B
#define OF_A 0
#define OF_B TILE_B
#define BUF_B (2 * TILE_B)         // 20480 B per stage
#define SMEM_TOTAL (2 * BUF_B)     // 40960 B

// ---------------- K0a: per-p scalar precompute ----------------
__global__ void precompute_a(const float* __restrict__ lLr, const float* __restrict__ Li,
                             const float* __restrict__ lDelta) {
    int p = threadIdx.x;
    double lamr = -exp((double)lLr[p]);
    double lami = (double)Li[p];
    double dt = exp((double)lDelta[p]);
    double lbr = lamr * dt, lbi = lami * dt;
    double er = exp(lbr);
    double Lr = er * cos(lbi), Limg = er * sin(lbi);
    g_Lam[p] = make_float2((float)Lr, (float)Limg);
    double eT = exp((double)T_CHK * lbr);
    g_LamT[p] = make_float2((float)(eT * cos((double)T_CHK * lbi)),
                            (float)(eT * sin((double)T_CHK * lbi)));
    double nr = Lr - 1.0, ni = Limg;
    double den = lamr * lamr + lami * lami;
    g_coeff[p] = make_float2((float)((nr * lamr + ni * lami) / den),
                             (float)((ni * lamr - nr * lami) / den));
}

// ---------------- K0b: pack weights into fp16 plane ----------------
__global__ __launch_bounds__(256) void precompute_w(
    const float* __restrict__ Br, const float* __restrict__ Bi,
    const float* __restrict__ Cr, const float* __restrict__ Ci) {
    int idx = blockIdx.x * 256 + threadIdx.x;  // 32768 = 128 h x 256 p
    int h = idx >> 8, p = idx & 255;
    float2 cf = g_coeff[p];
    float br = Br[p * H_TOT + h], bi = Bi[p * H_TOT + h];
    float w1v[2] = {cf.x * br - cf.y * bi, cf.x * bi + cf.y * br};
#pragma unroll
    for (int j = 0; j < 2; j++) {
        int n = 2 * p + j;
        g_W1h[(size_t)n * 128 + h] = __float2half_rn(w1v[j]);
    }
    float w2v[2] = {Cr[h * P_TOT + p], -Ci[h * P_TOT + p]};
#pragma unroll
    for (int j = 0; j < 2; j++) {
        int k = 2 * p + j;
        g_W2h[(size_t)h * 512 + k] = __float2half_rn(w2v[j]);
    }
}

// ---------------- shared MMA inner step (fp16 single-pass) ----------------
__device__ __forceinline__ void mma_chunk(uint32_t sbuf, int wm, int wn, int lane,
                                          float acc[2][8][4]) {
    int g = lane >> 3, rg = lane & 7;
#pragma unroll
    for (int kk = 0; kk < 2; kk++) {
        int k16 = kk * 16;
        uint32_t ah[2][4];
#pragma unroll
        for (int mt = 0; mt < 2; mt++) {
            int row = wm * 32 + mt * 16 + (g & 1) * 8 + rg;
            int col = k16 + (g >> 1) * 8;
            uint32_t a = sbuf + OF_A + row * 80 + col * 2;
            ldsm4(ah[mt][0], ah[mt][1], ah[mt][2], ah[mt][3], a);
        }
        uint32_t b[8][2];
        {
            int row = wn * 64 + (g >> 1) * 8 + rg;
            int col = k16 + (g & 1) * 8;
#pragma unroll
            for (int np = 0; np < 4; np++) {
                uint32_t ba = sbuf + OF_B + (row + np * 16) * 80 + col * 2;
                ldsm4(b[2 * np][0], b[2 * np][1], b[2 * np + 1][0], b[2 * np + 1][1], ba);
            }
#pragma unroll
            for (int mt = 0; mt < 2; mt++)
#pragma unroll
                for (int nt = 0; nt < 8; nt++)
                    mma16816(acc[mt][nt], ah[mt], b[nt]);
        }
    }
}

// ---------------- GEMM1: Bu = u @ W1 (M=65536, N=512, K=128; 4 kt) ----------------
__global__ __launch_bounds__(256, 2) void gemm1_mma(const float* __restrict__ u) {
    extern __shared__ char smem[];
    uint32_t sb = smem_u32(smem);
    int tid = threadIdx.x, lane = tid & 31, wid = tid >> 5;
    int gq = lane >> 2, tig = lane & 3;
    int wm = wid >> 1, wn = wid & 1;
    int bn = blockIdx.x * 128, bm = blockIdx.y * 128;

    float acc[2][8][4];
#pragma unroll
    for (int mt = 0; mt < 2; mt++)
#pragma unroll
        for (int nt = 0; nt < 8; nt++)
#pragma unroll
            for (int i = 0; i < 4; i++) acc[mt][nt][i] = 0.f;

    float4 areg[4];
#pragma unroll
    for (int i = 0; i < 4; i++) {
        int idx = tid + i * 256;
        int row = idx >> 3, c4 = (idx & 7) * 4;
        areg[i] = *(const float4*)(u + (size_t)(bm + row) * 128 + 0 + c4);
    }
#pragma unroll
    for (int i = 0; i < 2; i++) {
        int idx = tid + i * 256;
        int row = idx >> 2, seg = idx & 3;
        CP_ASYNC16(sb + OF_B + row * 80 + seg * 16,
                   g_W1h + (size_t)(bn + row) * 128 + seg * 8);
    }
    CP_COMMIT();

    for (int kt = 0; kt < 4; kt++) {
        int b = kt & 1;
        char* buf = smem + b * BUF_B;
#pragma unroll
        for (int i = 0; i < 4; i++) {
            int idx = tid + i * 256;
            int row = idx >> 3, c4 = (idx & 7) * 4;
            float4 v = areg[i];
            __half2 h01 = __halves2half2(__float2half_rn(v.x), __float2half_rn(v.y));
            __half2 h23 = __halves2half2(__float2half_rn(v.z), __float2half_rn(v.w));
            *(uint2*)(buf + OF_A + row * 80 + c4 * 2) =
                make_uint2(*(uint32_t*)&h01, *(uint32_t*)&h23);
        }
        if (kt < 3) {
#pragma unroll
            for (int i = 0; i < 4; i++) {
                int idx = tid + i * 256;
                int row = idx >> 3, c4 = (idx & 7) * 4;
                areg[i] = *(const float4*)(u + (size_t)(bm + row) * 128 + (kt + 1) * 32 + c4);
            }
        }
        CP_WAIT0();
        __syncthreads();
        if (kt < 3) {
            uint32_t nb = sb + (b ^ 1) * BUF_B;
#pragma unroll
            for (int i = 0; i < 2; i++) {
                int idx = tid + i * 256;
                int row = idx >> 2, seg = idx & 3;
                CP_ASYNC16(nb + OF_B + row * 80 + seg * 16,
                           g_W1h + (size_t)(bn + row) * 128 + (kt + 1) * 32 + seg * 8);
            }
            CP_COMMIT();
        }
        mma_chunk(sb + b * BUF_B, wm, wn, lane, acc);
    }
    // epilogue: pack (re,im) -> fp16x2 word, store at [r][p]
#pragma unroll
    for (int mt = 0; mt < 2; mt++)
#pragma unroll
        for (int nt = 0; nt < 8; nt++) {
            int r = bm + wm * 32 + mt * 16 + gq;
            int wi = (bn >> 1) + wn * 32 + nt * 4 + tig;   // global p word index
            __half2 w0 = __halves2half2(__float2half_rn(acc[mt][nt][0]),
                                        __float2half_rn(acc[mt][nt][1]));
            __half2 w1 = __halves2half2(__float2half_rn(acc[mt][nt][2]),
                                        __float2half_rn(acc[mt][nt][3]));
            g_Bu16[(size_t)r * 256 + wi] = *(uint32_t*)&w0;
            g_Bu16[(size_t)(r + 8) * 256 + wi] = *(uint32_t*)&w1;
        }
}

// ---------------- K2: per-chunk local scan (aggregates only, fp32 accum) ----------------
__global__ __launch_bounds__(256) void scan_local_kernel() {
    int p = threadIdx.x;
    int b = blockIdx.x % B_TOT;
    int c = blockIdx.x / B_TOT;
    float2 lam = g_Lam[p];
    float2 s = make_float2(0.f, 0.f);
    const uint32_t* base = g_Bu16 + ((size_t)(c * T_CHK) * B_TOT + b) * 256 + p;
    const size_t stride = (size_t)B_TOT * 256;
#pragma unroll 8
    for (int t = 0; t < T_CHK; t++) {
        float2 x = unpack_h2(base[t * stride]);
        s = cmul(lam, s);
        s.x += x.x; s.y += x.y;
    }
    g_Sloc[((size_t)c * B_TOT + b) * P_TOT + p] = s;
}

// ---------------- K3: final scan with inline prefix, emit fp16 words ----------------
__global__ __launch_bounds__(256) void scan_final_kernel() {
    int p = threadIdx.x;
    int b = blockIdx.x % B_TOT;
    int c = blockIdx.x / B_TOT;
    float2 lam = g_Lam[p];
    float2 s = make_float2(0.f, 0.f);
    {
        float2 lam64 = g_LamT[p];
        float2 f = make_float2(1.f, 0.f);
        for (int j = c - 1; j >= 0; j--) {
            float2 a = g_Sloc[((size_t)j * B_TOT + b) * P_TOT + p];
            float2 t = cmul(f, a);
            s.x += t.x; s.y += t.y;
            f = cmul(f, lam64);
        }
    }
    const uint32_t* base = g_Bu16 + ((size_t)(c * T_CHK) * B_TOT + b) * 256 + p;
    const size_t stride = (size_t)B_TOT * 256;
    size_t mbase = (size_t)(c * T_CHK) * B_TOT + b;
#pragma unroll 8
    for (int t = 0; t < T_CHK; t++) {
        float2 x = unpack_h2(base[t * stride]);
        s = cmul(lam, s);
        s.x += x.x; s.y += x.y;
        size_t m = mbase + (size_t)t * B_TOT;
        __half2 hh = __halves2half2(__float2half_rn(s.x), __float2half_rn(s.y));
        g_ohw[m * 256 + p] = *(uint32_t*)&hh;
    }
}

// ---------------- GEMM2: out = o @ W2 + D*u (M=65536, N=128, K=512; 16 kt) ----------------
__global__ __launch_bounds__(256, 2) void gemm2_mma(const float* __restrict__ u,
                                                    const float* __restrict__ Dv,
                                                    float* __restrict__ out) {
    extern __shared__ char smem[];
    uint32_t sb = smem_u32(smem);
    int tid = threadIdx.x, lane = tid & 31, wid = tid >> 5;
    int gq = lane >> 2, tig = lane & 3;
    int wm = wid >> 1, wn = wid & 1;
    int bm = blockIdx.x * 128;

    float acc[2][8][4];
#pragma unroll
    for (int mt = 0; mt < 2; mt++)
#pragma unroll
        for (int nt = 0; nt < 8; nt++)
#pragma unroll
            for (int i = 0; i < 4; i++) acc[mt][nt][i] = 0.f;

#pragma unroll
    for (int i = 0; i < 2; i++) {
        int idx = tid + i * 256;
        int row = idx >> 2, seg = idx & 3;
        CP_ASYNC16(sb + OF_A + row * 80 + seg * 16, g_ohw + (size_t)(bm + row) * 256 + seg * 4);
        CP_ASYNC16(sb + OF_B + row * 80 + seg * 16, g_W2h + (size_t)row * 512 + seg * 8);
    }
    CP_COMMIT();

    for (int kt = 0; kt < 16; kt++) {
        int b = kt & 1;
        CP_WAIT0();
        __syncthreads();
        if (kt < 15) {
            uint32_t nb = sb + (b ^ 1) * BUF_B;
            int kn = kt + 1;
#pragma unroll
            for (int i = 0; i < 2; i++) {
                int idx = tid + i * 256;
                int row = idx >> 2, seg = idx & 3;
                CP_ASYNC16(nb + OF_A + row * 80 + seg * 16,
                           g_ohw + (size_t)(bm + row) * 256 + kn * 16 + seg * 4);
                CP_ASYNC16(nb + OF_B + row * 80 + seg * 16,
                           g_W2h + (size_t)row * 512 + kn * 32 + seg * 8);
            }
            CP_COMMIT();
        }
        mma_chunk(sb + b * BUF_B, wm, wn, lane, acc);
    }
#pragma unroll
    for (int mt = 0; mt < 2; mt++)
#pragma unroll
        for (int nt = 0; nt < 8; nt++) {
            int c = wn * 64 + nt * 8 + 2 * tig;
            float2 dv = *(const float2*)(Dv + c);
#pragma unroll
            for (int half = 0; half < 2; half++) {
                int r = bm + wm * 32 + mt * 16 + gq + half * 8;
                float2 uv = *(const float2*)(u + (size_t)r * 128 + c);
                float2 o;
                o.x = acc[mt][nt][2 * half + 0] + dv.x * uv.x;
                o.y = acc[mt][nt][2 * half + 1] + dv.y * uv.y;
                *(float2*)&out[(size_t)r * 128 + c] = o;
            }
        }
}

// ---------------- launch ----------------
extern "C" void kernel_launch(void* const* d_in, const int* in_sizes, int n_in,
                              void* d_out, int out_size) {
    const float* u   = (const float*)d_in[0];
    const float* lLr = (const float*)d_in[1];
    const float* Li  = (const float*)d_in[2];
    const float* Br  = (const float*)d_in[3];
    const float* Bi  = (const float*)d_in[4];
    const float* Cr  = (const float*)d_in[5];
    const float* Ci  = (const float*)d_in[6];
    const float* Dv  = (const float*)d_in[7];
    const float* lDt = (const float*)d_in[8];
    float* out = (float*)d_out;

    cudaFuncSetAttribute(gemm1_mma, cudaFuncAttributeMaxDynamicSharedMemorySize, SMEM_TOTAL);
    cudaFuncSetAttribute(gemm2_mma, cudaFuncAttributeMaxDynamicSharedMemorySize, SMEM_TOTAL);

    precompute_a<<<1, 256>>>(lLr, Li, lDt);
    precompute_w<<<128, 256>>>(Br, Bi, Cr, Ci);

    gemm1_mma<<<dim3(4, M_TOT / 128), 256, SMEM_TOTAL>>>(u);

    scan_local_kernel<<<C_CHK * B_TOT, 256>>>();
    scan_final_kernel<<<C_CHK * B_TOT, 256>>>();

    gemm2_mma<<<M_TOT / 128, 256, SMEM_TOTAL>>>(u, Dv, out);
}